// round 1
// baseline (speedup 1.0000x reference)
#include <cuda_runtime.h>
#include <cuda_bf16.h>
#include <math.h>

// Problem constants
constexpr int BB = 2, RR = 64, CC = 2048, EE = 128, HH = 4, DH = 32;
constexpr long long MROWS = (long long)BB * RR * CC;        // 262144
constexpr long long QKV_ELEMS = MROWS * EE;                  // 33,554,432

// Scratch (device globals — no runtime allocation)
__device__ float g_q[QKV_ELEMS];
__device__ float g_k[QKV_ELEMS];
__device__ float g_v[QKV_ELEMS];
__device__ float g_ktv[BB * RR * HH * DH * DH];              // 2 MB
__device__ float g_ksum[BB * RR * HH * DH];                  // 64 KB

// ---------------------------------------------------------------------------
// Kernel 1: fused QKV projection + bias + (elu+1) for q,k
//   X: [M,128] row-major; W: [128(in),128(out)]; out[m][j] = sum_k X[m][k]*W[k][j] + b[j]
// Tile: 128 rows x 128 cols per block, 256 threads, 8x8 per thread.
// ---------------------------------------------------------------------------
__global__ __launch_bounds__(256)
void qkv_kernel(const float* __restrict__ X,
                const float* __restrict__ Wq, const float* __restrict__ bq,
                const float* __restrict__ Wk, const float* __restrict__ bk,
                const float* __restrict__ Wv, const float* __restrict__ bv)
{
    extern __shared__ float smem1[];
    float (*sX)[129] = (float (*)[129])smem1;                 // 128 x 129
    float (*sW)[128] = (float (*)[128])(smem1 + 128 * 129);   // 128 x 128

    const float* W;
    const float* bias;
    float* out;
    bool act;
    if (blockIdx.y == 0)      { W = Wq; bias = bq; out = g_q; act = true;  }
    else if (blockIdx.y == 1) { W = Wk; bias = bk; out = g_k; act = true;  }
    else                      { W = Wv; bias = bv; out = g_v; act = false; }

    const int tid = threadIdx.x;
    const long long m0 = (long long)blockIdx.x * 128;

    // Load X tile (coalesced float4 reads, scalar smem stores due to pad)
    {
        const float4* Xg = (const float4*)(X + m0 * EE);
        #pragma unroll
        for (int it = 0; it < 16; ++it) {
            int idx = tid + it * 256;            // 4096 float4 total
            int r = idx >> 5, c4 = idx & 31;
            float4 v = Xg[idx];
            sX[r][c4 * 4 + 0] = v.x;
            sX[r][c4 * 4 + 1] = v.y;
            sX[r][c4 * 4 + 2] = v.z;
            sX[r][c4 * 4 + 3] = v.w;
        }
        const float4* Wg = (const float4*)W;
        float4* sWg = (float4*)sW;
        #pragma unroll
        for (int it = 0; it < 16; ++it)
            sWg[tid + it * 256] = Wg[tid + it * 256];
    }
    __syncthreads();

    const int tx = tid & 15, ty = tid >> 4;
    const int c0 = tx * 8, r0 = ty * 8;

    float acc[8][8];
    #pragma unroll
    for (int i = 0; i < 8; ++i)
        #pragma unroll
        for (int j = 0; j < 8; ++j) acc[i][j] = 0.f;

    #pragma unroll 4
    for (int kk = 0; kk < 128; ++kk) {
        float a[8];
        #pragma unroll
        for (int i = 0; i < 8; ++i) a[i] = sX[r0 + i][kk];
        float4 w0 = *(const float4*)&sW[kk][c0];
        float4 w1 = *(const float4*)&sW[kk][c0 + 4];
        float b[8] = {w0.x, w0.y, w0.z, w0.w, w1.x, w1.y, w1.z, w1.w};
        #pragma unroll
        for (int i = 0; i < 8; ++i)
            #pragma unroll
            for (int j = 0; j < 8; ++j)
                acc[i][j] = fmaf(a[i], b[j], acc[i][j]);
    }

    // Epilogue: bias + optional elu+1, vectorized store
    #pragma unroll
    for (int i = 0; i < 8; ++i) {
        float* orow = out + (m0 + r0 + i) * EE + c0;
        float v[8];
        #pragma unroll
        for (int j = 0; j < 8; ++j) {
            float t = acc[i][j] + __ldg(bias + c0 + j);
            if (act) t = (t > 0.f) ? (t + 1.f) : expf(t);
            v[j] = t;
        }
        float4 o0 = {v[0], v[1], v[2], v[3]};
        float4 o1 = {v[4], v[5], v[6], v[7]};
        *(float4*)(orow)     = o0;
        *(float4*)(orow + 4) = o1;
    }
}

// ---------------------------------------------------------------------------
// Kernel 2: KtV[d][e] = sum_c k[c,d]*v[c,e]  and  ksum[d] = sum_c k[c,d]
// One block per (b,r,h) = 512 blocks, 256 threads; thread owns (d, 4 e's).
// ---------------------------------------------------------------------------
__global__ __launch_bounds__(256)
void ktv_kernel()
{
    __shared__ float sk[64][32];
    __shared__ float sv[64][32];

    const int blk = blockIdx.x;           // br*H + h
    const int h = blk & 3;
    const int br = blk >> 2;
    const long long base = (long long)br * CC * EE + h * DH;

    const int tid = threadIdx.x;
    const int d = tid & 31;
    const int eg = tid >> 5;              // 0..7 -> e = eg*4 .. eg*4+3

    float a0 = 0.f, a1 = 0.f, a2 = 0.f, a3 = 0.f, ks = 0.f;

    for (int c0 = 0; c0 < CC; c0 += 64) {
        __syncthreads();
        #pragma unroll
        for (int it = 0; it < 8; ++it) {
            int idx = tid + it * 256;     // 2048 elems per array
            int r = idx >> 5, c = idx & 31;
            long long g = base + (long long)(c0 + r) * EE + c;
            sk[r][c] = g_k[g];
            sv[r][c] = g_v[g];
        }
        __syncthreads();
        #pragma unroll 8
        for (int cc = 0; cc < 64; ++cc) {
            float kd = sk[cc][d];
            float4 ve = *(const float4*)&sv[cc][eg * 4];
            a0 = fmaf(kd, ve.x, a0);
            a1 = fmaf(kd, ve.y, a1);
            a2 = fmaf(kd, ve.z, a2);
            a3 = fmaf(kd, ve.w, a3);
            ks += kd;                      // same value for all eg; eg==0 stores
        }
    }

    float* ktv = g_ktv + (long long)blk * DH * DH;
    float4 o = {a0, a1, a2, a3};
    *(float4*)&ktv[d * 32 + eg * 4] = o;
    if (eg == 0) g_ksum[blk * 32 + d] = ks;
}

// ---------------------------------------------------------------------------
// Kernel 3: per (b,r) tile of 128 rows:
//   Z[r][h] = 1/(q[r,h,:].ksum[h,:] + eps)
//   t[r][h*32+e] = (sum_d q[r][h*32+d]*KtV[h][d][e]) * Z[r][h]
//   out[r][:] = t[r][:] @ Wo + bo
// ---------------------------------------------------------------------------
__global__ __launch_bounds__(256)
void out_kernel(const float* __restrict__ Wo, const float* __restrict__ bo,
                float* __restrict__ out)
{
    extern __shared__ float smem3[];
    float (*sQ)[129]      = (float (*)[129])smem3;                    // 128x129 (reused as t)
    float (*sWo)[128]     = (float (*)[128])(smem3 + 128 * 129);      // 128x128
    float (*sKtV)[32][32] = (float (*)[32][32])(smem3 + 128 * 129 + 128 * 128); // 4x32x32
    float* sKsum = smem3 + 128 * 129 + 128 * 128 + 4096;              // 128
    float* sBo   = sKsum + 128;                                       // 128
    float (*sZ)[4] = (float (*)[4])(sBo + 128);                       // 128x4

    const int blk = blockIdx.x;
    const int br = blk >> 4;              // (b*R + r)
    const int ct = blk & 15;
    const long long m0 = (long long)br * CC + ct * 128;

    const int tid = threadIdx.x;

    // Load q tile
    {
        const float4* Qg = (const float4*)(g_q + m0 * EE);
        #pragma unroll
        for (int it = 0; it < 16; ++it) {
            int idx = tid + it * 256;
            int r = idx >> 5, c4 = idx & 31;
            float4 v = Qg[idx];
            sQ[r][c4 * 4 + 0] = v.x;
            sQ[r][c4 * 4 + 1] = v.y;
            sQ[r][c4 * 4 + 2] = v.z;
            sQ[r][c4 * 4 + 3] = v.w;
        }
        const float4* Wg = (const float4*)Wo;
        float4* sWg = (float4*)sWo;
        #pragma unroll
        for (int it = 0; it < 16; ++it)
            sWg[tid + it * 256] = Wg[tid + it * 256];
        // KtV: 4096 floats
        const float4* Kg = (const float4*)(g_ktv + (long long)br * HH * DH * DH);
        float4* sKg = (float4*)sKtV;
        #pragma unroll
        for (int it = 0; it < 4; ++it)
            sKg[tid + it * 256] = Kg[tid + it * 256];
        if (tid < 128) {
            sKsum[tid] = g_ksum[br * 128 + tid];
            sBo[tid] = bo[tid];
        }
    }
    __syncthreads();

    // Z pass: 512 (row, head) values
    #pragma unroll
    for (int pass = 0; pass < 2; ++pass) {
        int idx = tid + pass * 256;
        int r = idx >> 2, h = idx & 3;
        float z = 0.f;
        #pragma unroll
        for (int d = 0; d < 32; ++d)
            z = fmaf(sQ[r][h * 32 + d], sKsum[h * 32 + d], z);
        sZ[r][h] = 1.0f / (z + 1e-6f);
    }
    __syncthreads();

    const int tx = tid & 15, ty = tid >> 4;
    const int c0 = tx * 8, r0 = ty * 8;
    const int hh = tx >> 2;               // head of this column group
    const int e0 = (tx & 3) * 8;          // e-offset within head

    // Step 1: t = (q @ KtV) * Z   (contraction over d = 32)
    float acc[8][8];
    #pragma unroll
    for (int i = 0; i < 8; ++i)
        #pragma unroll
        for (int j = 0; j < 8; ++j) acc[i][j] = 0.f;

    #pragma unroll 4
    for (int d = 0; d < 32; ++d) {
        float a[8];
        #pragma unroll
        for (int i = 0; i < 8; ++i) a[i] = sQ[r0 + i][hh * 32 + d];
        float4 w0 = *(const float4*)&sKtV[hh][d][e0];
        float4 w1 = *(const float4*)&sKtV[hh][d][e0 + 4];
        float b[8] = {w0.x, w0.y, w0.z, w0.w, w1.x, w1.y, w1.z, w1.w};
        #pragma unroll
        for (int i = 0; i < 8; ++i)
            #pragma unroll
            for (int j = 0; j < 8; ++j)
                acc[i][j] = fmaf(a[i], b[j], acc[i][j]);
    }
    float zrow[8];
    #pragma unroll
    for (int i = 0; i < 8; ++i) zrow[i] = sZ[r0 + i][hh];

    __syncthreads();   // everyone done reading q
    #pragma unroll
    for (int i = 0; i < 8; ++i)
        #pragma unroll
        for (int j = 0; j < 8; ++j)
            sQ[r0 + i][c0 + j] = acc[i][j] * zrow[i];   // sQ now holds t
    __syncthreads();

    // Step 2: out = t @ Wo + bo  (contraction over 128)
    #pragma unroll
    for (int i = 0; i < 8; ++i)
        #pragma unroll
        for (int j = 0; j < 8; ++j) acc[i][j] = 0.f;

    #pragma unroll 4
    for (int kk = 0; kk < 128; ++kk) {
        float a[8];
        #pragma unroll
        for (int i = 0; i < 8; ++i) a[i] = sQ[r0 + i][kk];
        float4 w0 = *(const float4*)&sWo[kk][c0];
        float4 w1 = *(const float4*)&sWo[kk][c0 + 4];
        float b[8] = {w0.x, w0.y, w0.z, w0.w, w1.x, w1.y, w1.z, w1.w};
        #pragma unroll
        for (int i = 0; i < 8; ++i)
            #pragma unroll
            for (int j = 0; j < 8; ++j)
                acc[i][j] = fmaf(a[i], b[j], acc[i][j]);
    }

    #pragma unroll
    for (int i = 0; i < 8; ++i) {
        float* orow = out + (m0 + r0 + i) * EE + c0;
        float4 o0 = {acc[i][0] + sBo[c0 + 0], acc[i][1] + sBo[c0 + 1],
                     acc[i][2] + sBo[c0 + 2], acc[i][3] + sBo[c0 + 3]};
        float4 o1 = {acc[i][4] + sBo[c0 + 4], acc[i][5] + sBo[c0 + 5],
                     acc[i][6] + sBo[c0 + 6], acc[i][7] + sBo[c0 + 7]};
        *(float4*)(orow)     = o0;
        *(float4*)(orow + 4) = o1;
    }
}

// ---------------------------------------------------------------------------
extern "C" void kernel_launch(void* const* d_in, const int* in_sizes, int n_in,
                              void* d_out, int out_size)
{
    const float* X  = (const float*)d_in[0];
    const float* Wq = (const float*)d_in[1];
    const float* bq = (const float*)d_in[2];
    const float* Wk = (const float*)d_in[3];
    const float* bk = (const float*)d_in[4];
    const float* Wv = (const float*)d_in[5];
    const float* bv = (const float*)d_in[6];
    const float* Wo = (const float*)d_in[7];
    const float* bo = (const float*)d_in[8];
    float* out = (float*)d_out;

    const int SMEM1 = (128 * 129 + 128 * 128) * sizeof(float);                  // 131584
    const int SMEM3 = (128 * 129 + 128 * 128 + 4096 + 128 + 128 + 512) * sizeof(float); // 151040

    cudaFuncSetAttribute(qkv_kernel, cudaFuncAttributeMaxDynamicSharedMemorySize, SMEM1);
    cudaFuncSetAttribute(out_kernel, cudaFuncAttributeMaxDynamicSharedMemorySize, SMEM3);

    qkv_kernel<<<dim3((unsigned)(MROWS / 128), 3), 256, SMEM1>>>(X, Wq, bq, Wk, bk, Wv, bv);
    ktv_kernel<<<BB * RR * HH, 256>>>();
    out_kernel<<<BB * RR * (CC / 128), 256, SMEM3>>>(Wo, bo, out);
}

// round 3
// speedup vs baseline: 1.3310x; 1.3310x over previous
#include <cuda_runtime.h>
#include <cuda_bf16.h>
#include <math.h>

typedef unsigned int u32;

// Problem constants
constexpr int BB = 2, RR = 64, CC = 2048, EE = 128, HH = 4, DH = 32;
constexpr long long MROWS = (long long)BB * RR * CC;        // 262144
constexpr long long QKV_ELEMS = MROWS * EE;                  // 33,554,432

// Scratch (device globals — no runtime allocation)
__device__ float g_q[QKV_ELEMS];
__device__ float g_k[QKV_ELEMS];
__device__ float g_v[QKV_ELEMS];
__device__ float g_ktv[BB * RR * HH * DH * DH];              // 2 MB
__device__ float g_ksum[BB * RR * HH * DH];                  // 64 KB

// ---------------------------------------------------------------------------
// helpers
// ---------------------------------------------------------------------------
__device__ __forceinline__ void ldsm4(u32 a, u32& r0, u32& r1, u32& r2, u32& r3) {
    asm volatile("ldmatrix.sync.aligned.m8n8.x4.shared.b16 {%0,%1,%2,%3},[%4];"
                 : "=r"(r0), "=r"(r1), "=r"(r2), "=r"(r3) : "r"(a));
}
__device__ __forceinline__ void ldsm4t(u32 a, u32& r0, u32& r1, u32& r2, u32& r3) {
    asm volatile("ldmatrix.sync.aligned.m8n8.x4.trans.shared.b16 {%0,%1,%2,%3},[%4];"
                 : "=r"(r0), "=r"(r1), "=r"(r2), "=r"(r3) : "r"(a));
}
__device__ __forceinline__ void mma_bf16(float c[4], u32 a0, u32 a1,
                                         u32 a2, u32 a3, u32 b0, u32 b1) {
    asm volatile(
        "mma.sync.aligned.m16n8k16.row.col.f32.bf16.bf16.f32 "
        "{%0,%1,%2,%3},{%4,%5,%6,%7},{%8,%9},{%0,%1,%2,%3};"
        : "+f"(c[0]), "+f"(c[1]), "+f"(c[2]), "+f"(c[3])
        : "r"(a0), "r"(a1), "r"(a2), "r"(a3), "r"(b0), "r"(b1));
}

// Convert 8 consecutive floats to hi/lo bf16 packed as uint4 each.
__device__ __forceinline__ void cvt8(const float* f, uint4& hi, uint4& lo) {
    u32 h[4];
    u32 l[4];
#pragma unroll
    for (int i = 0; i < 4; ++i) {
        float a = f[2 * i];
        float b = f[2 * i + 1];
        __nv_bfloat16 ah16 = __float2bfloat16_rn(a);
        __nv_bfloat16 bh16 = __float2bfloat16_rn(b);
        float ar = a - __bfloat162float(ah16);
        float br = b - __bfloat162float(bh16);
        __nv_bfloat162 hp = __halves2bfloat162(ah16, bh16);
        __nv_bfloat162 lp = __floats2bfloat162_rn(ar, br);
        h[i] = *(u32*)&hp;
        l[i] = *(u32*)&lp;
    }
    hi = make_uint4(h[0], h[1], h[2], h[3]);
    lo = make_uint4(l[0], l[1], l[2], l[3]);
}

__device__ __forceinline__ float elu1(float x) {
    return (x > 0.f) ? (x + 1.f) : expf(x);
}

// smem layout (bytes): Xhi[0,32K) Xlo[32K,64K) Whi[64K,96K) Wlo[96K,128K)
constexpr int SOFF_XHI = 0;
constexpr int SOFF_XLO = 32768;
constexpr int SOFF_WHI = 65536;
constexpr int SOFF_WLO = 98304;
constexpr int SMEM_QKV = 131072;

// ---------------------------------------------------------------------------
// Kernel 1: fused QKV projection via bf16 hi/lo tensor-core mma (3xBF16 split).
// One block = 128 rows of X * all 128 cols, loops over the 3 weight matrices.
// 256 threads = 8 warps (4x2), warp tile 32x64, mma m16n8k16.
// ---------------------------------------------------------------------------
__global__ __launch_bounds__(256)
void qkv_mma_kernel(const float* __restrict__ X,
                    const float* __restrict__ Wq, const float* __restrict__ bq,
                    const float* __restrict__ Wk, const float* __restrict__ bk,
                    const float* __restrict__ Wv, const float* __restrict__ bv)
{
    extern __shared__ char smem[];
    const u32 sb = (u32)__cvta_generic_to_shared(smem);

    const int tid = threadIdx.x;
    const int lane = tid & 31;
    const int w = tid >> 5;
    const long long m0 = (long long)blockIdx.x * 128;

    // ---- Load + convert X tile (128x128 f32 -> bf16 hi/lo, swizzled) ----
    {
        const float4* Xg = (const float4*)(X + m0 * EE);
#pragma unroll
        for (int it = 0; it < 8; ++it) {
            int idx = tid + it * 256;            // 2048 chunks (row, ch)
            int row = idx >> 4;
            int ch = idx & 15;
            float4 f0 = Xg[row * 32 + ch * 2];
            float4 f1 = Xg[row * 32 + ch * 2 + 1];
            float f[8] = {f0.x, f0.y, f0.z, f0.w, f1.x, f1.y, f1.z, f1.w};
            uint4 hi, lo;
            cvt8(f, hi, lo);
            int off = row * 256 + ((ch ^ (row & 7)) << 4);
            *(uint4*)(smem + SOFF_XHI + off) = hi;
            *(uint4*)(smem + SOFF_XLO + off) = lo;
        }
    }

    // ---- per-thread ldmatrix address pieces ----
    const int wr0 = (w & 3) * 32;          // warp row origin
    const int wc0 = (w >> 2) * 64;         // warp col origin
    const int quad = lane >> 3;
    const int l7 = lane & 7;
    int arow0 = wr0 + l7 + (quad & 1) * 8;
    int arow1 = arow0 + 16;
    const int axor0 = arow0 & 7;
    const int axor1 = arow1 & 7;
    const int ac_off = quad >> 1;
    const int krow_base = l7 + (quad & 1) * 8;   // + ks*16
    const int bxor = krow_base & 7;
    const int g = lane >> 2;
    const int t2 = lane & 3;

    const float* Wlist[3] = {Wq, Wk, Wv};
    const float* blist[3] = {bq, bk, bv};

#pragma unroll 1
    for (int j = 0; j < 3; ++j) {
        __syncthreads();   // prior iteration's reads of sW done / X stores pending
        // ---- Load + convert W_j (k-major [128][128]) ----
        {
            const float4* Wg = (const float4*)Wlist[j];
#pragma unroll
            for (int it = 0; it < 8; ++it) {
                int idx = tid + it * 256;
                int row = idx >> 4;
                int ch = idx & 15;
                float4 f0 = Wg[row * 32 + ch * 2];
                float4 f1 = Wg[row * 32 + ch * 2 + 1];
                float f[8] = {f0.x, f0.y, f0.z, f0.w, f1.x, f1.y, f1.z, f1.w};
                uint4 hi, lo;
                cvt8(f, hi, lo);
                int off = row * 256 + ((ch ^ (row & 7)) << 4);
                *(uint4*)(smem + SOFF_WHI + off) = hi;
                *(uint4*)(smem + SOFF_WLO + off) = lo;
            }
        }
        __syncthreads();

        float acc[2][8][4];
#pragma unroll
        for (int ii = 0; ii < 2; ++ii)
#pragma unroll
            for (int jj = 0; jj < 8; ++jj)
#pragma unroll
                for (int kk = 0; kk < 4; ++kk) acc[ii][jj][kk] = 0.f;

#pragma unroll 1
        for (int ks = 0; ks < 8; ++ks) {
            u32 ah0[4], ah1[4], al0[4], al1[4];
            {
                int offA0 = arow0 * 256 + (((ks * 2 + ac_off) ^ axor0) << 4);
                int offA1 = arow1 * 256 + (((ks * 2 + ac_off) ^ axor1) << 4);
                ldsm4(sb + SOFF_XHI + offA0, ah0[0], ah0[1], ah0[2], ah0[3]);
                ldsm4(sb + SOFF_XLO + offA0, al0[0], al0[1], al0[2], al0[3]);
                ldsm4(sb + SOFF_XHI + offA1, ah1[0], ah1[1], ah1[2], ah1[3]);
                ldsm4(sb + SOFF_XLO + offA1, al1[0], al1[1], al1[2], al1[3]);
            }
#pragma unroll
            for (int p = 0; p < 4; ++p) {
                int chB = (wc0 >> 3) + p * 2 + (quad >> 1);
                int offB = (ks * 16 + krow_base) * 256 + ((chB ^ bxor) << 4);
                u32 wb0, wb1, wb2, wb3;
                ldsm4t(sb + SOFF_WHI + offB, wb0, wb1, wb2, wb3);
                mma_bf16(acc[0][2 * p],     ah0[0], ah0[1], ah0[2], ah0[3], wb0, wb1);
                mma_bf16(acc[0][2 * p + 1], ah0[0], ah0[1], ah0[2], ah0[3], wb2, wb3);
                mma_bf16(acc[1][2 * p],     ah1[0], ah1[1], ah1[2], ah1[3], wb0, wb1);
                mma_bf16(acc[1][2 * p + 1], ah1[0], ah1[1], ah1[2], ah1[3], wb2, wb3);
                mma_bf16(acc[0][2 * p],     al0[0], al0[1], al0[2], al0[3], wb0, wb1);
                mma_bf16(acc[0][2 * p + 1], al0[0], al0[1], al0[2], al0[3], wb2, wb3);
                mma_bf16(acc[1][2 * p],     al1[0], al1[1], al1[2], al1[3], wb0, wb1);
                mma_bf16(acc[1][2 * p + 1], al1[0], al1[1], al1[2], al1[3], wb2, wb3);
                ldsm4t(sb + SOFF_WLO + offB, wb0, wb1, wb2, wb3);
                mma_bf16(acc[0][2 * p],     ah0[0], ah0[1], ah0[2], ah0[3], wb0, wb1);
                mma_bf16(acc[0][2 * p + 1], ah0[0], ah0[1], ah0[2], ah0[3], wb2, wb3);
                mma_bf16(acc[1][2 * p],     ah1[0], ah1[1], ah1[2], ah1[3], wb0, wb1);
                mma_bf16(acc[1][2 * p + 1], ah1[0], ah1[1], ah1[2], ah1[3], wb2, wb3);
            }
        }

        // ---- epilogue: bias (+ elu+1 for q,k), store to global scratch ----
        float* outp = (j == 0) ? g_q : (j == 1) ? g_k : g_v;
        const float* bias = blist[j];
        const bool act = (j < 2);
#pragma unroll
        for (int mt = 0; mt < 2; ++mt) {
#pragma unroll
            for (int nt = 0; nt < 8; ++nt) {
                int col = wc0 + nt * 8 + t2 * 2;
                float2 bb = *(const float2*)(bias + col);
                long long r0g = m0 + wr0 + mt * 16 + g;
                float v0 = acc[mt][nt][0] + bb.x;
                float v1 = acc[mt][nt][1] + bb.y;
                float v2 = acc[mt][nt][2] + bb.x;
                float v3 = acc[mt][nt][3] + bb.y;
                if (act) { v0 = elu1(v0); v1 = elu1(v1); v2 = elu1(v2); v3 = elu1(v3); }
                *(float2*)(outp + r0g * EE + col)       = make_float2(v0, v1);
                *(float2*)(outp + (r0g + 8) * EE + col) = make_float2(v2, v3);
            }
        }
    }
}

// ---------------------------------------------------------------------------
// Kernel 2: KtV[d][e] = sum_c k[c,d]*v[c,e]  and  ksum[d] = sum_c k[c,d]
// ---------------------------------------------------------------------------
__global__ __launch_bounds__(256)
void ktv_kernel()
{
    __shared__ float sk[64][32];
    __shared__ float sv[64][32];

    const int blk = blockIdx.x;           // br*H + h
    const int h = blk & 3;
    const int br = blk >> 2;
    const long long base = (long long)br * CC * EE + h * DH;

    const int tid = threadIdx.x;
    const int d = tid & 31;
    const int eg = tid >> 5;              // 0..7 -> e = eg*4 .. eg*4+3

    float a0 = 0.f, a1 = 0.f, a2 = 0.f, a3 = 0.f, ks = 0.f;

    for (int c0 = 0; c0 < CC; c0 += 64) {
        __syncthreads();
        #pragma unroll
        for (int it = 0; it < 8; ++it) {
            int idx = tid + it * 256;     // 2048 elems per array
            int r = idx >> 5;
            int c = idx & 31;
            long long gi = base + (long long)(c0 + r) * EE + c;
            sk[r][c] = g_k[gi];
            sv[r][c] = g_v[gi];
        }
        __syncthreads();
        #pragma unroll 8
        for (int cc = 0; cc < 64; ++cc) {
            float kd = sk[cc][d];
            float4 ve = *(const float4*)&sv[cc][eg * 4];
            a0 = fmaf(kd, ve.x, a0);
            a1 = fmaf(kd, ve.y, a1);
            a2 = fmaf(kd, ve.z, a2);
            a3 = fmaf(kd, ve.w, a3);
            ks += kd;
        }
    }

    float* ktv = g_ktv + (long long)blk * DH * DH;
    float4 o = {a0, a1, a2, a3};
    *(float4*)&ktv[d * 32 + eg * 4] = o;
    if (eg == 0) g_ksum[blk * 32 + d] = ks;
}

// ---------------------------------------------------------------------------
// Kernel 3: Z, q@KtV, and output projection
// ---------------------------------------------------------------------------
__global__ __launch_bounds__(256)
void out_kernel(const float* __restrict__ Wo, const float* __restrict__ bo,
                float* __restrict__ out)
{
    extern __shared__ float smem3[];
    float (*sQ)[129]      = (float (*)[129])smem3;                    // 128x129 (reused as t)
    float (*sWo)[128]     = (float (*)[128])(smem3 + 128 * 129);      // 128x128
    float (*sKtV)[32][32] = (float (*)[32][32])(smem3 + 128 * 129 + 128 * 128); // 4x32x32
    float* sKsum = smem3 + 128 * 129 + 128 * 128 + 4096;              // 128
    float* sBo   = sKsum + 128;                                       // 128
    float (*sZ)[4] = (float (*)[4])(sBo + 128);                       // 128x4

    const int blk = blockIdx.x;
    const int br = blk >> 4;              // (b*R + r)
    const int ct = blk & 15;
    const long long m0 = (long long)br * CC + ct * 128;

    const int tid = threadIdx.x;

    // Load q tile
    {
        const float4* Qg = (const float4*)(g_q + m0 * EE);
        #pragma unroll
        for (int it = 0; it < 16; ++it) {
            int idx = tid + it * 256;
            int r = idx >> 5;
            int c4 = idx & 31;
            float4 v = Qg[idx];
            sQ[r][c4 * 4 + 0] = v.x;
            sQ[r][c4 * 4 + 1] = v.y;
            sQ[r][c4 * 4 + 2] = v.z;
            sQ[r][c4 * 4 + 3] = v.w;
        }
        const float4* Wg = (const float4*)Wo;
        float4* sWg = (float4*)sWo;
        #pragma unroll
        for (int it = 0; it < 16; ++it)
            sWg[tid + it * 256] = Wg[tid + it * 256];
        const float4* Kg = (const float4*)(g_ktv + (long long)br * HH * DH * DH);
        float4* sKg = (float4*)sKtV;
        #pragma unroll
        for (int it = 0; it < 4; ++it)
            sKg[tid + it * 256] = Kg[tid + it * 256];
        if (tid < 128) {
            sKsum[tid] = g_ksum[br * 128 + tid];
            sBo[tid] = bo[tid];
        }
    }
    __syncthreads();

    // Z pass: 512 (row, head) values
    #pragma unroll
    for (int pass = 0; pass < 2; ++pass) {
        int idx = tid + pass * 256;
        int r = idx >> 2;
        int h = idx & 3;
        float z = 0.f;
        #pragma unroll
        for (int d = 0; d < 32; ++d)
            z = fmaf(sQ[r][h * 32 + d], sKsum[h * 32 + d], z);
        sZ[r][h] = 1.0f / (z + 1e-6f);
    }
    __syncthreads();

    const int tx = tid & 15, ty = tid >> 4;
    const int c0 = tx * 8, r0 = ty * 8;
    const int hh = tx >> 2;
    const int e0 = (tx & 3) * 8;

    // Step 1: t = (q @ KtV) * Z
    float acc[8][8];
    #pragma unroll
    for (int i = 0; i < 8; ++i)
        #pragma unroll
        for (int j = 0; j < 8; ++j) acc[i][j] = 0.f;

    #pragma unroll 4
    for (int d = 0; d < 32; ++d) {
        float a[8];
        #pragma unroll
        for (int i = 0; i < 8; ++i) a[i] = sQ[r0 + i][hh * 32 + d];
        float4 w0 = *(const float4*)&sKtV[hh][d][e0];
        float4 w1 = *(const float4*)&sKtV[hh][d][e0 + 4];
        float b[8] = {w0.x, w0.y, w0.z, w0.w, w1.x, w1.y, w1.z, w1.w};
        #pragma unroll
        for (int i = 0; i < 8; ++i)
            #pragma unroll
            for (int j = 0; j < 8; ++j)
                acc[i][j] = fmaf(a[i], b[j], acc[i][j]);
    }
    float zrow[8];
    #pragma unroll
    for (int i = 0; i < 8; ++i) zrow[i] = sZ[r0 + i][hh];

    __syncthreads();
    #pragma unroll
    for (int i = 0; i < 8; ++i)
        #pragma unroll
        for (int j = 0; j < 8; ++j)
            sQ[r0 + i][c0 + j] = acc[i][j] * zrow[i];
    __syncthreads();

    // Step 2: out = t @ Wo + bo
    #pragma unroll
    for (int i = 0; i < 8; ++i)
        #pragma unroll
        for (int j = 0; j < 8; ++j) acc[i][j] = 0.f;

    #pragma unroll 4
    for (int kk = 0; kk < 128; ++kk) {
        float a[8];
        #pragma unroll
        for (int i = 0; i < 8; ++i) a[i] = sQ[r0 + i][kk];
        float4 w0 = *(const float4*)&sWo[kk][c0];
        float4 w1 = *(const float4*)&sWo[kk][c0 + 4];
        float b[8] = {w0.x, w0.y, w0.z, w0.w, w1.x, w1.y, w1.z, w1.w};
        #pragma unroll
        for (int i = 0; i < 8; ++i)
            #pragma unroll
            for (int j = 0; j < 8; ++j)
                acc[i][j] = fmaf(a[i], b[j], acc[i][j]);
    }

    #pragma unroll
    for (int i = 0; i < 8; ++i) {
        float* orow = out + (m0 + r0 + i) * EE + c0;
        float4 o0 = {acc[i][0] + sBo[c0 + 0], acc[i][1] + sBo[c0 + 1],
                     acc[i][2] + sBo[c0 + 2], acc[i][3] + sBo[c0 + 3]};
        float4 o1 = {acc[i][4] + sBo[c0 + 4], acc[i][5] + sBo[c0 + 5],
                     acc[i][6] + sBo[c0 + 6], acc[i][7] + sBo[c0 + 7]};
        *(float4*)(orow)     = o0;
        *(float4*)(orow + 4) = o1;
    }
}

// ---------------------------------------------------------------------------
extern "C" void kernel_launch(void* const* d_in, const int* in_sizes, int n_in,
                              void* d_out, int out_size)
{
    const float* X  = (const float*)d_in[0];
    const float* Wq = (const float*)d_in[1];
    const float* bq = (const float*)d_in[2];
    const float* Wk = (const float*)d_in[3];
    const float* bk = (const float*)d_in[4];
    const float* Wv = (const float*)d_in[5];
    const float* bv = (const float*)d_in[6];
    const float* Wo = (const float*)d_in[7];
    const float* bo = (const float*)d_in[8];
    float* out = (float*)d_out;

    const int SMEM3 = (128 * 129 + 128 * 128 + 4096 + 128 + 128 + 512) * sizeof(float);

    cudaFuncSetAttribute(qkv_mma_kernel, cudaFuncAttributeMaxDynamicSharedMemorySize, SMEM_QKV);
    cudaFuncSetAttribute(out_kernel, cudaFuncAttributeMaxDynamicSharedMemorySize, SMEM3);

    qkv_mma_kernel<<<(unsigned)(MROWS / 128), 256, SMEM_QKV>>>(X, Wq, bq, Wk, bk, Wv, bv);
    ktv_kernel<<<BB * RR * HH, 256>>>();
    out_kernel<<<BB * RR * (CC / 128), 256, SMEM3>>>(Wo, bo, out);
}

// round 4
// speedup vs baseline: 1.9327x; 1.4521x over previous
#include <cuda_runtime.h>
#include <cuda_bf16.h>
#include <math.h>

typedef unsigned int u32;

// Problem constants
constexpr int BB = 2, RR = 64, CC = 2048, EE = 128, HH = 4, DH = 32;
constexpr long long MROWS = (long long)BB * RR * CC;        // 262144
constexpr long long QKV_ELEMS = MROWS * EE;                  // 33,554,432
constexpr int NTILES = (int)(MROWS / 64);                    // 4096

// Scratch (device globals — no runtime allocation)
__device__ float g_q[QKV_ELEMS];
__device__ float g_k[QKV_ELEMS];
__device__ float g_v[QKV_ELEMS];
__device__ float g_ktv[BB * RR * HH * DH * DH];              // 2 MB
__device__ float g_ksum[BB * RR * HH * DH];                  // 64 KB
// Pre-swizzled bf16 weight images: [matrix 0..3][hi 2048 | lo 2048] uint4 chunks
__device__ uint4 g_wimg[4 * 4096];
// Pre-swizzled bf16 t images: per 64-row tile: [hi 1024 | lo 1024] uint4
__device__ uint4 g_timg[(long long)NTILES * 2048];

// ---------------------------------------------------------------------------
// helpers
// ---------------------------------------------------------------------------
__device__ __forceinline__ void ldsm4(u32 a, u32& r0, u32& r1, u32& r2, u32& r3) {
    asm volatile("ldmatrix.sync.aligned.m8n8.x4.shared.b16 {%0,%1,%2,%3},[%4];"
                 : "=r"(r0), "=r"(r1), "=r"(r2), "=r"(r3) : "r"(a));
}
__device__ __forceinline__ void ldsm4t(u32 a, u32& r0, u32& r1, u32& r2, u32& r3) {
    asm volatile("ldmatrix.sync.aligned.m8n8.x4.trans.shared.b16 {%0,%1,%2,%3},[%4];"
                 : "=r"(r0), "=r"(r1), "=r"(r2), "=r"(r3) : "r"(a));
}
__device__ __forceinline__ void mma_bf16(float c[4], u32 a0, u32 a1,
                                         u32 a2, u32 a3, u32 b0, u32 b1) {
    asm volatile(
        "mma.sync.aligned.m16n8k16.row.col.f32.bf16.bf16.f32 "
        "{%0,%1,%2,%3},{%4,%5,%6,%7},{%8,%9},{%0,%1,%2,%3};"
        : "+f"(c[0]), "+f"(c[1]), "+f"(c[2]), "+f"(c[3])
        : "r"(a0), "r"(a1), "r"(a2), "r"(a3), "r"(b0), "r"(b1));
}

// Convert 8 consecutive floats to hi/lo bf16 packed as uint4 each.
__device__ __forceinline__ void cvt8(const float* f, uint4& hi, uint4& lo) {
    u32 h[4];
    u32 l[4];
#pragma unroll
    for (int i = 0; i < 4; ++i) {
        float a = f[2 * i];
        float b = f[2 * i + 1];
        __nv_bfloat16 ah16 = __float2bfloat16_rn(a);
        __nv_bfloat16 bh16 = __float2bfloat16_rn(b);
        float ar = a - __bfloat162float(ah16);
        float br = b - __bfloat162float(bh16);
        __nv_bfloat162 hp = __halves2bfloat162(ah16, bh16);
        __nv_bfloat162 lp = __floats2bfloat162_rn(ar, br);
        h[i] = *(u32*)&hp;
        l[i] = *(u32*)&lp;
    }
    hi = make_uint4(h[0], h[1], h[2], h[3]);
    lo = make_uint4(l[0], l[1], l[2], l[3]);
}

__device__ __forceinline__ float elu1(float x) {
    return (x > 0.f) ? (x + 1.f) : expf(x);
}

// smem layout (bytes) for GEMM kernels: Ahi[0,16K) Alo[16K,32K) Whi[32K,64K) Wlo[64K,96K)
constexpr int SOFF_AHI = 0;
constexpr int SOFF_ALO = 16384;
constexpr int SOFF_WHI = 32768;
constexpr int SOFF_WLO = 65536;
constexpr int SMEM_GEMM = 98304;

// ---------------------------------------------------------------------------
// Kernel 0: precompute bf16 hi/lo swizzled images of the 4 weight matrices.
// ---------------------------------------------------------------------------
__global__ __launch_bounds__(256)
void prep_w_kernel(const float* __restrict__ Wq, const float* __restrict__ Wk,
                   const float* __restrict__ Wv, const float* __restrict__ Wo)
{
    const float* Ws[4] = {Wq, Wk, Wv, Wo};
    const float4* W = (const float4*)Ws[blockIdx.x];
    uint4* dst = g_wimg + blockIdx.x * 4096;
    const int tid = threadIdx.x;
#pragma unroll
    for (int it = 0; it < 8; ++it) {
        int idx = tid + it * 256;            // 2048 chunks
        int row = idx >> 4;
        int ch = idx & 15;
        float4 f0 = W[row * 32 + ch * 2];
        float4 f1 = W[row * 32 + ch * 2 + 1];
        float f[8] = {f0.x, f0.y, f0.z, f0.w, f1.x, f1.y, f1.z, f1.w};
        uint4 hi, lo;
        cvt8(f, hi, lo);
        int c = row * 16 + (ch ^ (row & 7));
        dst[c] = hi;
        dst[2048 + c] = lo;
    }
}

// ---------------------------------------------------------------------------
// Kernel 1: fused QKV projection via bf16 hi/lo tensor-core mma (3-term split).
// One block = 64 rows of X, all 128 cols, loops over the 3 weight matrices.
// 256 threads = 8 warps (2x4), warp tile 32x32, mma m16n8k16. 2 CTAs/SM.
// ---------------------------------------------------------------------------
__global__ __launch_bounds__(256, 2)
void qkv_mma_kernel(const float* __restrict__ X,
                    const float* __restrict__ bq,
                    const float* __restrict__ bk,
                    const float* __restrict__ bv)
{
    extern __shared__ char smem[];
    const u32 sb = (u32)__cvta_generic_to_shared(smem);

    const int tid = threadIdx.x;
    const int lane = tid & 31;
    const int w = tid >> 5;
    const long long m0 = (long long)blockIdx.x * 64;

    // ---- Load + convert X tile (64x128 f32 -> bf16 hi/lo, swizzled) ----
    {
        const float4* Xg = (const float4*)(X + m0 * EE);
#pragma unroll
        for (int it = 0; it < 4; ++it) {
            int idx = tid + it * 256;            // 1024 chunks (row, ch)
            int row = idx >> 4;
            int ch = idx & 15;
            float4 f0 = Xg[row * 32 + ch * 2];
            float4 f1 = Xg[row * 32 + ch * 2 + 1];
            float f[8] = {f0.x, f0.y, f0.z, f0.w, f1.x, f1.y, f1.z, f1.w};
            uint4 hi, lo;
            cvt8(f, hi, lo);
            int off = row * 256 + ((ch ^ (row & 7)) << 4);
            *(uint4*)(smem + SOFF_AHI + off) = hi;
            *(uint4*)(smem + SOFF_ALO + off) = lo;
        }
    }

    // ---- per-thread ldmatrix address pieces ----
    const int wr0 = (w & 1) * 32;          // warp row origin (M=64 -> 2 warp rows)
    const int wc0 = (w >> 1) * 32;         // warp col origin (N=128 -> 4 warp cols)
    const int quad = lane >> 3;
    const int l7 = lane & 7;
    const int arow0 = wr0 + l7 + (quad & 1) * 8;
    const int arow1 = arow0 + 16;
    const int axor0 = arow0 & 7;
    const int axor1 = arow1 & 7;
    const int ac_off = quad >> 1;
    const int krow_base = l7 + (quad & 1) * 8;   // + ks*16
    const int bxor = krow_base & 7;
    const int g = lane >> 2;
    const int t2 = lane & 3;

    const float* blist[3] = {bq, bk, bv};

#pragma unroll 1
    for (int j = 0; j < 3; ++j) {
        __syncthreads();   // prior iteration's reads of sW done / A stores pending
        // ---- Copy pre-swizzled W_j image into smem ----
        {
            const uint4* src = g_wimg + j * 4096;
#pragma unroll
            for (int it = 0; it < 8; ++it) {
                int i = tid + it * 256;          // 2048 chunks each
                *(uint4*)(smem + SOFF_WHI + i * 16) = src[i];
                *(uint4*)(smem + SOFF_WLO + i * 16) = src[2048 + i];
            }
        }
        __syncthreads();

        float acc[2][4][4];
#pragma unroll
        for (int ii = 0; ii < 2; ++ii)
#pragma unroll
            for (int jj = 0; jj < 4; ++jj)
#pragma unroll
                for (int kk = 0; kk < 4; ++kk) acc[ii][jj][kk] = 0.f;

#pragma unroll 1
        for (int ks = 0; ks < 8; ++ks) {
            u32 ah0[4], ah1[4], al0[4], al1[4];
            {
                int offA0 = arow0 * 256 + (((ks * 2 + ac_off) ^ axor0) << 4);
                int offA1 = arow1 * 256 + (((ks * 2 + ac_off) ^ axor1) << 4);
                ldsm4(sb + SOFF_AHI + offA0, ah0[0], ah0[1], ah0[2], ah0[3]);
                ldsm4(sb + SOFF_ALO + offA0, al0[0], al0[1], al0[2], al0[3]);
                ldsm4(sb + SOFF_AHI + offA1, ah1[0], ah1[1], ah1[2], ah1[3]);
                ldsm4(sb + SOFF_ALO + offA1, al1[0], al1[1], al1[2], al1[3]);
            }
#pragma unroll
            for (int p = 0; p < 2; ++p) {
                int chB = (wc0 >> 3) + p * 2 + (quad >> 1);
                int offB = (ks * 16 + krow_base) * 256 + ((chB ^ bxor) << 4);
                u32 wb0, wb1, wb2, wb3;
                ldsm4t(sb + SOFF_WHI + offB, wb0, wb1, wb2, wb3);
                mma_bf16(acc[0][2 * p],     ah0[0], ah0[1], ah0[2], ah0[3], wb0, wb1);
                mma_bf16(acc[0][2 * p + 1], ah0[0], ah0[1], ah0[2], ah0[3], wb2, wb3);
                mma_bf16(acc[1][2 * p],     ah1[0], ah1[1], ah1[2], ah1[3], wb0, wb1);
                mma_bf16(acc[1][2 * p + 1], ah1[0], ah1[1], ah1[2], ah1[3], wb2, wb3);
                mma_bf16(acc[0][2 * p],     al0[0], al0[1], al0[2], al0[3], wb0, wb1);
                mma_bf16(acc[0][2 * p + 1], al0[0], al0[1], al0[2], al0[3], wb2, wb3);
                mma_bf16(acc[1][2 * p],     al1[0], al1[1], al1[2], al1[3], wb0, wb1);
                mma_bf16(acc[1][2 * p + 1], al1[0], al1[1], al1[2], al1[3], wb2, wb3);
                ldsm4t(sb + SOFF_WLO + offB, wb0, wb1, wb2, wb3);
                mma_bf16(acc[0][2 * p],     ah0[0], ah0[1], ah0[2], ah0[3], wb0, wb1);
                mma_bf16(acc[0][2 * p + 1], ah0[0], ah0[1], ah0[2], ah0[3], wb2, wb3);
                mma_bf16(acc[1][2 * p],     ah1[0], ah1[1], ah1[2], ah1[3], wb0, wb1);
                mma_bf16(acc[1][2 * p + 1], ah1[0], ah1[1], ah1[2], ah1[3], wb2, wb3);
            }
        }

        // ---- epilogue: bias (+ elu+1 for q,k), store to global scratch ----
        float* outp = (j == 0) ? g_q : (j == 1) ? g_k : g_v;
        const float* bias = blist[j];
        const bool act = (j < 2);
#pragma unroll
        for (int mt = 0; mt < 2; ++mt) {
#pragma unroll
            for (int nt = 0; nt < 4; ++nt) {
                int col = wc0 + nt * 8 + t2 * 2;
                float2 bb = *(const float2*)(bias + col);
                long long r0g = m0 + wr0 + mt * 16 + g;
                float v0 = acc[mt][nt][0] + bb.x;
                float v1 = acc[mt][nt][1] + bb.y;
                float v2 = acc[mt][nt][2] + bb.x;
                float v3 = acc[mt][nt][3] + bb.y;
                if (act) { v0 = elu1(v0); v1 = elu1(v1); v2 = elu1(v2); v3 = elu1(v3); }
                *(float2*)(outp + r0g * EE + col)       = make_float2(v0, v1);
                *(float2*)(outp + (r0g + 8) * EE + col) = make_float2(v2, v3);
            }
        }
    }
}

// ---------------------------------------------------------------------------
// Kernel 2: KtV[d][e] = sum_c k[c,d]*v[c,e]  and  ksum[d] = sum_c k[c,d]
// ---------------------------------------------------------------------------
__global__ __launch_bounds__(256)
void ktv_kernel()
{
    __shared__ float sk[64][32];
    __shared__ float sv[64][32];

    const int blk = blockIdx.x;           // br*H + h
    const int h = blk & 3;
    const int br = blk >> 2;
    const long long base = (long long)br * CC * EE + h * DH;

    const int tid = threadIdx.x;
    const int d = tid & 31;
    const int eg = tid >> 5;              // 0..7 -> e = eg*4 .. eg*4+3

    float a0 = 0.f, a1 = 0.f, a2 = 0.f, a3 = 0.f, ks = 0.f;

    for (int c0 = 0; c0 < CC; c0 += 64) {
        __syncthreads();
        #pragma unroll
        for (int it = 0; it < 8; ++it) {
            int idx = tid + it * 256;     // 2048 elems per array
            int r = idx >> 5;
            int c = idx & 31;
            long long gi = base + (long long)(c0 + r) * EE + c;
            sk[r][c] = g_k[gi];
            sv[r][c] = g_v[gi];
        }
        __syncthreads();
        #pragma unroll 8
        for (int cc = 0; cc < 64; ++cc) {
            float kd = sk[cc][d];
            float4 ve = *(const float4*)&sv[cc][eg * 4];
            a0 = fmaf(kd, ve.x, a0);
            a1 = fmaf(kd, ve.y, a1);
            a2 = fmaf(kd, ve.z, a2);
            a3 = fmaf(kd, ve.w, a3);
            ks += kd;
        }
    }

    float* ktv = g_ktv + (long long)blk * DH * DH;
    float4 o = {a0, a1, a2, a3};
    *(float4*)&ktv[d * 32 + eg * 4] = o;
    if (eg == 0) g_ksum[blk * 32 + d] = ks;
}

// ---------------------------------------------------------------------------
// Kernel 3a: t = (q @ KtV) * Z, written as pre-swizzled bf16 hi/lo images.
// One block = 128 rows; 256 threads, thread tile 8x8 FFMA (depth-32).
// ---------------------------------------------------------------------------
__global__ __launch_bounds__(256, 2)
void t_kernel()
{
    extern __shared__ float smem3[];
    float (*sQ)[129]      = (float (*)[129])smem3;                    // 128x129
    float (*sKtV)[32][32] = (float (*)[32][32])(smem3 + 128 * 129);   // 4x32x32
    float* sKsum = smem3 + 128 * 129 + 4096;                          // 128
    float (*sZ)[4] = (float (*)[4])(sKsum + 128);                     // 128x4

    const int blk = blockIdx.x;
    const int br = blk >> 4;              // (b*R + r)
    const int ct = blk & 15;
    const long long m0 = (long long)br * CC + ct * 128;

    const int tid = threadIdx.x;

    // Load q tile + KtV + ksum
    {
        const float4* Qg = (const float4*)(g_q + m0 * EE);
        #pragma unroll
        for (int it = 0; it < 16; ++it) {
            int idx = tid + it * 256;
            int r = idx >> 5;
            int c4 = idx & 31;
            float4 v = Qg[idx];
            sQ[r][c4 * 4 + 0] = v.x;
            sQ[r][c4 * 4 + 1] = v.y;
            sQ[r][c4 * 4 + 2] = v.z;
            sQ[r][c4 * 4 + 3] = v.w;
        }
        const float4* Kg = (const float4*)(g_ktv + (long long)br * HH * DH * DH);
        float4* sKg = (float4*)sKtV;
        #pragma unroll
        for (int it = 0; it < 4; ++it)
            sKg[tid + it * 256] = Kg[tid + it * 256];
        if (tid < 128) sKsum[tid] = g_ksum[br * 128 + tid];
    }
    __syncthreads();

    // Z pass: 512 (row, head) values
    #pragma unroll
    for (int pass = 0; pass < 2; ++pass) {
        int idx = tid + pass * 256;
        int r = idx >> 2;
        int h = idx & 3;
        float z = 0.f;
        #pragma unroll
        for (int d = 0; d < 32; ++d)
            z = fmaf(sQ[r][h * 32 + d], sKsum[h * 32 + d], z);
        sZ[r][h] = 1.0f / (z + 1e-6f);
    }
    __syncthreads();

    const int tx = tid & 15, ty = tid >> 4;
    const int c0 = tx * 8, r0 = ty * 8;
    const int hh = tx >> 2;
    const int e0 = (tx & 3) * 8;

    float acc[8][8];
    #pragma unroll
    for (int i = 0; i < 8; ++i)
        #pragma unroll
        for (int j = 0; j < 8; ++j) acc[i][j] = 0.f;

    #pragma unroll 4
    for (int d = 0; d < 32; ++d) {
        float a[8];
        #pragma unroll
        for (int i = 0; i < 8; ++i) a[i] = sQ[r0 + i][hh * 32 + d];
        float4 w0 = *(const float4*)&sKtV[hh][d][e0];
        float4 w1 = *(const float4*)&sKtV[hh][d][e0 + 4];
        float b[8] = {w0.x, w0.y, w0.z, w0.w, w1.x, w1.y, w1.z, w1.w};
        #pragma unroll
        for (int i = 0; i < 8; ++i)
            #pragma unroll
            for (int j = 0; j < 8; ++j)
                acc[i][j] = fmaf(a[i], b[j], acc[i][j]);
    }

    // scale by Z, convert to bf16 hi/lo, store swizzled image chunks
    const long long tile0 = (m0 >> 6);
    #pragma unroll
    for (int i = 0; i < 8; ++i) {
        float z = sZ[r0 + i][hh];
        float v[8];
        #pragma unroll
        for (int j = 0; j < 8; ++j) v[j] = acc[i][j] * z;
        uint4 hi, lo;
        cvt8(v, hi, lo);
        int rr = r0 + i;                      // 0..127
        long long tile = tile0 + (rr >> 6);
        int lrow = rr & 63;
        int chunk = lrow * 16 + (tx ^ (lrow & 7));
        g_timg[tile * 2048 + chunk] = hi;
        g_timg[tile * 2048 + 1024 + chunk] = lo;
    }
}

// ---------------------------------------------------------------------------
// Kernel 3b: out = t @ Wo + bo via bf16 hi/lo mma. Same structure as qkv.
// ---------------------------------------------------------------------------
__global__ __launch_bounds__(256, 2)
void out_mma_kernel(const float* __restrict__ bo, float* __restrict__ out)
{
    extern __shared__ char smem[];
    const u32 sb = (u32)__cvta_generic_to_shared(smem);

    const int tid = threadIdx.x;
    const int lane = tid & 31;
    const int w = tid >> 5;
    const long long tile = blockIdx.x;
    const long long m0 = tile * 64;

    // ---- Copy pre-swizzled t and Wo images into smem ----
    {
        const uint4* tsrc = g_timg + tile * 2048;
#pragma unroll
        for (int it = 0; it < 4; ++it) {
            int i = tid + it * 256;          // 1024 chunks each
            *(uint4*)(smem + SOFF_AHI + i * 16) = tsrc[i];
            *(uint4*)(smem + SOFF_ALO + i * 16) = tsrc[1024 + i];
        }
        const uint4* wsrc = g_wimg + 3 * 4096;
#pragma unroll
        for (int it = 0; it < 8; ++it) {
            int i = tid + it * 256;          // 2048 chunks each
            *(uint4*)(smem + SOFF_WHI + i * 16) = wsrc[i];
            *(uint4*)(smem + SOFF_WLO + i * 16) = wsrc[2048 + i];
        }
    }
    __syncthreads();

    const int wr0 = (w & 1) * 32;
    const int wc0 = (w >> 1) * 32;
    const int quad = lane >> 3;
    const int l7 = lane & 7;
    const int arow0 = wr0 + l7 + (quad & 1) * 8;
    const int arow1 = arow0 + 16;
    const int axor0 = arow0 & 7;
    const int axor1 = arow1 & 7;
    const int ac_off = quad >> 1;
    const int krow_base = l7 + (quad & 1) * 8;
    const int bxor = krow_base & 7;
    const int g = lane >> 2;
    const int t2 = lane & 3;

    float acc[2][4][4];
#pragma unroll
    for (int ii = 0; ii < 2; ++ii)
#pragma unroll
        for (int jj = 0; jj < 4; ++jj)
#pragma unroll
            for (int kk = 0; kk < 4; ++kk) acc[ii][jj][kk] = 0.f;

#pragma unroll 1
    for (int ks = 0; ks < 8; ++ks) {
        u32 ah0[4], ah1[4], al0[4], al1[4];
        {
            int offA0 = arow0 * 256 + (((ks * 2 + ac_off) ^ axor0) << 4);
            int offA1 = arow1 * 256 + (((ks * 2 + ac_off) ^ axor1) << 4);
            ldsm4(sb + SOFF_AHI + offA0, ah0[0], ah0[1], ah0[2], ah0[3]);
            ldsm4(sb + SOFF_ALO + offA0, al0[0], al0[1], al0[2], al0[3]);
            ldsm4(sb + SOFF_AHI + offA1, ah1[0], ah1[1], ah1[2], ah1[3]);
            ldsm4(sb + SOFF_ALO + offA1, al1[0], al1[1], al1[2], al1[3]);
        }
#pragma unroll
        for (int p = 0; p < 2; ++p) {
            int chB = (wc0 >> 3) + p * 2 + (quad >> 1);
            int offB = (ks * 16 + krow_base) * 256 + ((chB ^ bxor) << 4);
            u32 wb0, wb1, wb2, wb3;
            ldsm4t(sb + SOFF_WHI + offB, wb0, wb1, wb2, wb3);
            mma_bf16(acc[0][2 * p],     ah0[0], ah0[1], ah0[2], ah0[3], wb0, wb1);
            mma_bf16(acc[0][2 * p + 1], ah0[0], ah0[1], ah0[2], ah0[3], wb2, wb3);
            mma_bf16(acc[1][2 * p],     ah1[0], ah1[1], ah1[2], ah1[3], wb0, wb1);
            mma_bf16(acc[1][2 * p + 1], ah1[0], ah1[1], ah1[2], ah1[3], wb2, wb3);
            mma_bf16(acc[0][2 * p],     al0[0], al0[1], al0[2], al0[3], wb0, wb1);
            mma_bf16(acc[0][2 * p + 1], al0[0], al0[1], al0[2], al0[3], wb2, wb3);
            mma_bf16(acc[1][2 * p],     al1[0], al1[1], al1[2], al1[3], wb0, wb1);
            mma_bf16(acc[1][2 * p + 1], al1[0], al1[1], al1[2], al1[3], wb2, wb3);
            ldsm4t(sb + SOFF_WLO + offB, wb0, wb1, wb2, wb3);
            mma_bf16(acc[0][2 * p],     ah0[0], ah0[1], ah0[2], ah0[3], wb0, wb1);
            mma_bf16(acc[0][2 * p + 1], ah0[0], ah0[1], ah0[2], ah0[3], wb2, wb3);
            mma_bf16(acc[1][2 * p],     ah1[0], ah1[1], ah1[2], ah1[3], wb0, wb1);
            mma_bf16(acc[1][2 * p + 1], ah1[0], ah1[1], ah1[2], ah1[3], wb2, wb3);
        }
    }

    // epilogue: + bo, store f32
#pragma unroll
    for (int mt = 0; mt < 2; ++mt) {
#pragma unroll
        for (int nt = 0; nt < 4; ++nt) {
            int col = wc0 + nt * 8 + t2 * 2;
            float2 bb = *(const float2*)(bo + col);
            long long r0g = m0 + wr0 + mt * 16 + g;
            float v0 = acc[mt][nt][0] + bb.x;
            float v1 = acc[mt][nt][1] + bb.y;
            float v2 = acc[mt][nt][2] + bb.x;
            float v3 = acc[mt][nt][3] + bb.y;
            *(float2*)(out + r0g * EE + col)       = make_float2(v0, v1);
            *(float2*)(out + (r0g + 8) * EE + col) = make_float2(v2, v3);
        }
    }
}

// ---------------------------------------------------------------------------
extern "C" void kernel_launch(void* const* d_in, const int* in_sizes, int n_in,
                              void* d_out, int out_size)
{
    const float* X  = (const float*)d_in[0];
    const float* Wq = (const float*)d_in[1];
    const float* bq = (const float*)d_in[2];
    const float* Wk = (const float*)d_in[3];
    const float* bk = (const float*)d_in[4];
    const float* Wv = (const float*)d_in[5];
    const float* bv = (const float*)d_in[6];
    const float* Wo = (const float*)d_in[7];
    const float* bo = (const float*)d_in[8];
    float* out = (float*)d_out;

    const int SMEM_T = (128 * 129 + 4096 + 128 + 512) * sizeof(float);

    cudaFuncSetAttribute(qkv_mma_kernel, cudaFuncAttributeMaxDynamicSharedMemorySize, SMEM_GEMM);
    cudaFuncSetAttribute(out_mma_kernel, cudaFuncAttributeMaxDynamicSharedMemorySize, SMEM_GEMM);
    cudaFuncSetAttribute(t_kernel, cudaFuncAttributeMaxDynamicSharedMemorySize, SMEM_T);

    prep_w_kernel<<<4, 256>>>(Wq, Wk, Wv, Wo);
    qkv_mma_kernel<<<NTILES, 256, SMEM_GEMM>>>(X, bq, bk, bv);
    ktv_kernel<<<BB * RR * HH, 256>>>();
    t_kernel<<<BB * RR * (CC / 128), 256, SMEM_T>>>();
    out_mma_kernel<<<NTILES, 256, SMEM_GEMM>>>(bo, out);
}